// round 5
// baseline (speedup 1.0000x reference)
#include <cuda_runtime.h>

#define NB   32
#define NCH  16
#define NP   65536              // 256*256 pixels per batch
#define NPIX (NB * NP)

// ---------------- scratch (device globals; no allocation allowed) ----------
// pass1 partials: [tensor][batch][block][ a0[16] | aAll[16] | cnt ]
__device__ float g_p1[2][NB][32][33];
__device__ float g_w[NB][2][16];    // combined weight  m0*rd0 - m1*rd1  per tensor/channel
__device__ float g_p2[NB][32];      // pass2 per-block MSE partials

__device__ __forceinline__ float warp_sum(float v) {
#pragma unroll
    for (int off = 16; off; off >>= 1)
        v += __shfl_xor_sync(0xffffffffu, v, off);
    return v;
}

// ---------------- pass 1: class-conditional sums of normalized features ----
// grid (32, NB, 2), 256 threads. z selects tensor. float2 pixels, 4 iters.
__global__ __launch_bounds__(256, 3) void k_pass1(const float* __restrict__ S,
                                                  const float* __restrict__ T,
                                                  const int* __restrict__ tg) {
    const int bx  = blockIdx.x;
    const int b   = blockIdx.y;
    const int t   = blockIdx.z;
    const int tid = threadIdx.x;
    const float* X = t ? T : S;

    const float2* Xv = (const float2*)(X + (size_t)b * NCH * NP);
    const int2*   tv = (const int2*)(tg + (size_t)b * NP);

    float a0[NCH], aA[NCH];
#pragma unroll
    for (int c = 0; c < NCH; c++) { a0[c] = 0.f; aA[c] = 0.f; }
    float cnt = 0.f;

#pragma unroll 1
    for (int it = 0; it < 4; it++) {
        int p2 = (it * 32 + bx) * 256 + tid;       // float2 index in [0, NP/2)
        int2 tt = tv[p2];
        float mx = (tt.x == 0) ? 1.f : 0.f;
        float my = (tt.y == 0) ? 1.f : 0.f;
        cnt += mx + my;

        float2 v[NCH];
#pragma unroll
        for (int c = 0; c < NCH; c++) v[c] = Xv[c * (NP / 2) + p2];

        float ssx = 0.f, ssy = 0.f;
#pragma unroll
        for (int c = 0; c < NCH; c++) {
            ssx = fmaf(v[c].x, v[c].x, ssx);
            ssy = fmaf(v[c].y, v[c].y, ssy);
        }
        // equals x / max(sqrt(ss), 1e-12) for representable inputs
        float ix = rsqrtf(fmaxf(ssx, 1e-24f));
        float iy = rsqrtf(fmaxf(ssy, 1e-24f));
        float wx = mx * ix, wy = my * iy;
#pragma unroll
        for (int c = 0; c < NCH; c++) {
            aA[c] = fmaf(v[c].y, iy, fmaf(v[c].x, ix, aA[c]));
            a0[c] = fmaf(v[c].y, wy, fmaf(v[c].x, wx, a0[c]));
        }
    }

    // block reduce 33 stats -> g_p1 (plain stores, no global atomics)
    __shared__ float sred[33];
    if (tid < 33) sred[tid] = 0.f;
    __syncthreads();
    bool lane0 = ((tid & 31) == 0);
#pragma unroll
    for (int c = 0; c < NCH; c++) {
        float r0 = warp_sum(a0[c]);
        float rA = warp_sum(aA[c]);
        if (lane0) { atomicAdd(&sred[c], r0); atomicAdd(&sred[16 + c], rA); }
    }
    float rc = warp_sum(cnt);
    if (lane0) atomicAdd(&sred[32], rc);
    __syncthreads();
    if (tid < 33) g_p1[t][b][bx][tid] = sred[tid];
}

// ---------------- means -> combined per-channel weights --------------------
// grid NB, 128 threads
__global__ void k_means() {
    const int b = blockIdx.x;
    const int tid = threadIdx.x;
    __shared__ float ssum[2][33];
    __shared__ float smw[2][2][16];   // m*rd with class sign folded

    if (tid < 66) {
        int t = tid / 33, s = tid % 33;
        float acc = 0.f;
#pragma unroll 1
        for (int bx = 0; bx < 32; bx++) acc += g_p1[t][b][bx][s];
        ssum[t][s] = acc;
    }
    __syncthreads();

    if (tid < 64) {
        int t = tid >> 5, cls = (tid >> 4) & 1, c = tid & 15;
        float cnt0 = ssum[0][32];
        float s0 = ssum[t][c], sA = ssum[t][16 + c];
        float m = (cls == 0) ? s0 / (cnt0 + 1e-6f)
                             : (sA - s0) / ((float)NP - cnt0 + 1e-6f);
        // ||mean|| over channels: 16-lane butterfly (stays inside the warp)
        float n = m * m;
#pragma unroll
        for (int off = 8; off; off >>= 1)
            n += __shfl_xor_sync(0xffffffffu, n, off);
        float rd = 1.0f / fmaxf(sqrtf(n), 1e-8f);
        smw[t][cls][c] = (cls == 0) ? m * rd : -(m * rd);
    }
    __syncthreads();
    if (tid < 32) {
        int t = tid >> 4, c = tid & 15;
        g_w[b][t][c] = smw[t][0][c] + smw[t][1][c];
    }
}

// ---------------- pass 2: per-pixel pcsim difference + MSE -----------------
// grid (32, NB), 256 threads, float4 pixels, 2 iters
__global__ __launch_bounds__(256, 4) void k_pass2(const float* __restrict__ S,
                                                  const float* __restrict__ T,
                                                  const int* __restrict__ tg) {
    __shared__ float sw[32];          // [tensor][channel]
    __shared__ float sred[8];
    const int bx  = blockIdx.x;
    const int b   = blockIdx.y;
    const int tid = threadIdx.x;
    if (tid < 32) sw[tid] = ((const float*)g_w)[b * 32 + tid];
    __syncthreads();

    const float4* Sv = (const float4*)(S + (size_t)b * NCH * NP);
    const float4* Tv = (const float4*)(T + (size_t)b * NCH * NP);
    const int4*   tv = (const int4*)(tg + (size_t)b * NP);

    float local = 0.f;
#pragma unroll 1
    for (int it = 0; it < 2; it++) {
        int p4 = (it * 32 + bx) * 256 + tid;     // float4 index in [0, NP/4)
        int4 tt = tv[p4];
        float sx = (tt.x == 0) ? 1.f : -1.f;
        float sy = (tt.y == 0) ? 1.f : -1.f;
        float sz = (tt.z == 0) ? 1.f : -1.f;
        float sw4 = (tt.w == 0) ? 1.f : -1.f;

        float ssx = 0.f, ssy = 0.f, ssz = 0.f, ssw = 0.f;
        float dx = 0.f, dy = 0.f, dz = 0.f, dw = 0.f;
#pragma unroll
        for (int c = 0; c < NCH; c++) {
            float4 v = Sv[c * (NP / 4) + p4];
            float w = sw[c];
            ssx = fmaf(v.x, v.x, ssx); dx = fmaf(v.x, w, dx);
            ssy = fmaf(v.y, v.y, ssy); dy = fmaf(v.y, w, dy);
            ssz = fmaf(v.z, v.z, ssz); dz = fmaf(v.z, w, dz);
            ssw = fmaf(v.w, v.w, ssw); dw = fmaf(v.w, w, dw);
        }
        float pSx = __expf(sx  * dx * rsqrtf(fmaxf(ssx, 1e-24f)));
        float pSy = __expf(sy  * dy * rsqrtf(fmaxf(ssy, 1e-24f)));
        float pSz = __expf(sz  * dz * rsqrtf(fmaxf(ssz, 1e-24f)));
        float pSw = __expf(sw4 * dw * rsqrtf(fmaxf(ssw, 1e-24f)));

        ssx = ssy = ssz = ssw = 0.f;
        dx = dy = dz = dw = 0.f;
#pragma unroll
        for (int c = 0; c < NCH; c++) {
            float4 v = Tv[c * (NP / 4) + p4];
            float w = sw[16 + c];
            ssx = fmaf(v.x, v.x, ssx); dx = fmaf(v.x, w, dx);
            ssy = fmaf(v.y, v.y, ssy); dy = fmaf(v.y, w, dy);
            ssz = fmaf(v.z, v.z, ssz); dz = fmaf(v.z, w, dz);
            ssw = fmaf(v.w, v.w, ssw); dw = fmaf(v.w, w, dw);
        }
        float ex = pSx - __expf(sx  * dx * rsqrtf(fmaxf(ssx, 1e-24f)));
        float ey = pSy - __expf(sy  * dy * rsqrtf(fmaxf(ssy, 1e-24f)));
        float ez = pSz - __expf(sz  * dz * rsqrtf(fmaxf(ssz, 1e-24f)));
        float ew = pSw - __expf(sw4 * dw * rsqrtf(fmaxf(ssw, 1e-24f)));

        local = fmaf(ex, ex, local);
        local = fmaf(ey, ey, local);
        local = fmaf(ez, ez, local);
        local = fmaf(ew, ew, local);
    }

    local = warp_sum(local);
    if ((tid & 31) == 0) sred[tid >> 5] = local;
    __syncthreads();
    if (tid == 0) {
        float v = ((sred[0] + sred[1]) + (sred[2] + sred[3]))
                + ((sred[4] + sred[5]) + (sred[6] + sred[7]));
        g_p2[b][bx] = v;
    }
}

// ---------------- final reduction ------------------------------------------
__global__ void k_fin(float* __restrict__ out) {
    __shared__ float sred[8];
    int tid = threadIdx.x;            // 256 threads, 1024 partials
    const float* p = (const float*)g_p2;
    float v = (p[tid] + p[tid + 256]) + (p[tid + 512] + p[tid + 768]);
    v = warp_sum(v);
    if ((tid & 31) == 0) sred[tid >> 5] = v;
    __syncthreads();
    if (tid == 0) {
        float s = ((sred[0] + sred[1]) + (sred[2] + sred[3]))
                + ((sred[4] + sred[5]) + (sred[6] + sred[7]));
        out[0] = s * (1.0f / (float)NPIX);
    }
}

extern "C" void kernel_launch(void* const* d_in, const int* in_sizes, int n_in,
                              void* d_out, int out_size) {
    const float* S = (const float*)d_in[0];
    const float* T = (const float*)d_in[1];
    const int* tg = (const int*)d_in[2];
    float* out = (float*)d_out;

    dim3 g1(32, NB, 2);
    k_pass1<<<g1, 256>>>(S, T, tg);
    k_means<<<NB, 128>>>();
    dim3 g2(32, NB);
    k_pass2<<<g2, 256>>>(S, T, tg);
    k_fin<<<1, 256>>>(out);
}

// round 6
// speedup vs baseline: 1.1058x; 1.1058x over previous
#include <cuda_runtime.h>

#define NB   32
#define NCH  16
#define NP   65536              // 256*256 pixels per batch
#define NPIX (NB * NP)

// ---------------- scratch (device globals; no allocation allowed) ----------
// pass1 partials: [tensor][batch][block][ a0[16] | aAll[16] | cnt ]
__device__ float g_p1[2][NB][32][33];
__device__ float g_p2[NB][32];      // pass2 per-block MSE partials
__device__ int   g_ctr;             // last-block-done counter (self-resetting)

__device__ __forceinline__ float warp_sum(float v) {
#pragma unroll
    for (int off = 16; off; off >>= 1)
        v += __shfl_xor_sync(0xffffffffu, v, off);
    return v;
}

// ---------------- pass 1: class-conditional sums of normalized features ----
// grid (32, NB, 2), 256 threads. z selects tensor. float4 pixels, 2 iters.
__global__ __launch_bounds__(256, 2) void k_pass1(const float* __restrict__ S,
                                                  const float* __restrict__ T,
                                                  const int* __restrict__ tg) {
    const int bx  = blockIdx.x;
    const int b   = blockIdx.y;
    const int t   = blockIdx.z;
    const int tid = threadIdx.x;
    const float* X = t ? T : S;

    const float4* Xv = (const float4*)(X + (size_t)b * NCH * NP);
    const int4*   tv = (const int4*)(tg + (size_t)b * NP);

    float a0[NCH], aA[NCH];
#pragma unroll
    for (int c = 0; c < NCH; c++) { a0[c] = 0.f; aA[c] = 0.f; }
    float cnt = 0.f;

#pragma unroll 1
    for (int it = 0; it < 2; it++) {
        int p4 = (it * 32 + bx) * 256 + tid;       // float4 index in [0, NP/4)
        int4 tt = tv[p4];
        float mx = (tt.x == 0) ? 1.f : 0.f;
        float my = (tt.y == 0) ? 1.f : 0.f;
        float mz = (tt.z == 0) ? 1.f : 0.f;
        float mw = (tt.w == 0) ? 1.f : 0.f;
        cnt += (mx + my) + (mz + mw);

        float4 v[NCH];
#pragma unroll
        for (int c = 0; c < NCH; c++) v[c] = Xv[c * (NP / 4) + p4];

        float ssx = 0.f, ssy = 0.f, ssz = 0.f, ssw = 0.f;
#pragma unroll
        for (int c = 0; c < NCH; c++) {
            ssx = fmaf(v[c].x, v[c].x, ssx);
            ssy = fmaf(v[c].y, v[c].y, ssy);
            ssz = fmaf(v[c].z, v[c].z, ssz);
            ssw = fmaf(v[c].w, v[c].w, ssw);
        }
        // equals x / max(sqrt(ss), 1e-12) for representable inputs
        float ix = rsqrtf(fmaxf(ssx, 1e-24f));
        float iy = rsqrtf(fmaxf(ssy, 1e-24f));
        float iz = rsqrtf(fmaxf(ssz, 1e-24f));
        float iw = rsqrtf(fmaxf(ssw, 1e-24f));
        float wx = mx * ix, wy = my * iy, wz = mz * iz, ww = mw * iw;
#pragma unroll
        for (int c = 0; c < NCH; c++) {
            aA[c] = fmaf(v[c].w, iw, fmaf(v[c].z, iz, fmaf(v[c].y, iy, fmaf(v[c].x, ix, aA[c]))));
            a0[c] = fmaf(v[c].w, ww, fmaf(v[c].z, wz, fmaf(v[c].y, wy, fmaf(v[c].x, wx, a0[c]))));
        }
    }

    // block reduce 33 stats -> g_p1 (plain stores, no global atomics)
    __shared__ float sred[33];
    if (tid < 33) sred[tid] = 0.f;
    __syncthreads();
    bool lane0 = ((tid & 31) == 0);
#pragma unroll
    for (int c = 0; c < NCH; c++) {
        float r0 = warp_sum(a0[c]);
        float rA = warp_sum(aA[c]);
        if (lane0) { atomicAdd(&sred[c], r0); atomicAdd(&sred[16 + c], rA); }
    }
    float rc = warp_sum(cnt);
    if (lane0) atomicAdd(&sred[32], rc);
    __syncthreads();
    if (tid < 33) g_p1[t][b][bx][tid] = sred[tid];
}

// ---------------- pass 2: means prologue + pcsim + MSE + finalize ----------
// grid (32, NB), 256 threads, float4 pixels, 2 iters
__global__ __launch_bounds__(256, 4) void k_pass2(const float* __restrict__ S,
                                                  const float* __restrict__ T,
                                                  const int* __restrict__ tg,
                                                  float* __restrict__ out) {
    __shared__ float ssum[66];
    __shared__ float sw[32];          // combined weight per [tensor][channel]
    __shared__ float sred[8];
    __shared__ int   slast;
    const int bx  = blockIdx.x;
    const int b   = blockIdx.y;
    const int tid = threadIdx.x;

    // --- prologue: reduce pass1 partials -> combined weights (redundant/block)
    if (tid < 66) {
        int t = tid / 33, s = tid - t * 33;
        float acc = 0.f;
#pragma unroll
        for (int k = 0; k < 32; k++) acc += g_p1[t][b][k][s];
        ssum[tid] = acc;
    }
    __syncthreads();
    if (tid < 64) {
        int t = tid >> 5, cls = (tid >> 4) & 1, c = tid & 15;
        float cnt0 = ssum[32];                     // count from tensor 0
        float s0 = ssum[t * 33 + c], sA = ssum[t * 33 + 16 + c];
        float m = (cls == 0) ? s0 / (cnt0 + 1e-6f)
                             : (sA - s0) / ((float)NP - cnt0 + 1e-6f);
        float n = m * m;                           // ||mean|| over 16 channels
#pragma unroll
        for (int off = 8; off; off >>= 1)
            n += __shfl_xor_sync(0xffffffffu, n, off);
        float rd = 1.0f / fmaxf(sqrtf(n), 1e-8f);
        float val = (cls == 0) ? m * rd : -(m * rd);
        float other = __shfl_xor_sync(0xffffffffu, val, 16);   // combine classes
        if (cls == 0) sw[t * 16 + c] = val + other;
    }
    __syncthreads();

    const float4* Sv = (const float4*)(S + (size_t)b * NCH * NP);
    const float4* Tv = (const float4*)(T + (size_t)b * NCH * NP);
    const int4*   tv = (const int4*)(tg + (size_t)b * NP);

    float local = 0.f;
#pragma unroll 1
    for (int it = 0; it < 2; it++) {
        int p4 = (it * 32 + bx) * 256 + tid;     // float4 index in [0, NP/4)
        int4 tt = tv[p4];
        float sx = (tt.x == 0) ? 1.f : -1.f;
        float sy = (tt.y == 0) ? 1.f : -1.f;
        float sz = (tt.z == 0) ? 1.f : -1.f;
        float sw4 = (tt.w == 0) ? 1.f : -1.f;

        float ssx = 0.f, ssy = 0.f, ssz = 0.f, ssw = 0.f;
        float dx = 0.f, dy = 0.f, dz = 0.f, dw = 0.f;
#pragma unroll
        for (int c = 0; c < NCH; c++) {
            float4 v = Sv[c * (NP / 4) + p4];
            float w = sw[c];
            ssx = fmaf(v.x, v.x, ssx); dx = fmaf(v.x, w, dx);
            ssy = fmaf(v.y, v.y, ssy); dy = fmaf(v.y, w, dy);
            ssz = fmaf(v.z, v.z, ssz); dz = fmaf(v.z, w, dz);
            ssw = fmaf(v.w, v.w, ssw); dw = fmaf(v.w, w, dw);
        }
        float pSx = __expf(sx  * dx * rsqrtf(fmaxf(ssx, 1e-24f)));
        float pSy = __expf(sy  * dy * rsqrtf(fmaxf(ssy, 1e-24f)));
        float pSz = __expf(sz  * dz * rsqrtf(fmaxf(ssz, 1e-24f)));
        float pSw = __expf(sw4 * dw * rsqrtf(fmaxf(ssw, 1e-24f)));

        ssx = ssy = ssz = ssw = 0.f;
        dx = dy = dz = dw = 0.f;
#pragma unroll
        for (int c = 0; c < NCH; c++) {
            float4 v = Tv[c * (NP / 4) + p4];
            float w = sw[16 + c];
            ssx = fmaf(v.x, v.x, ssx); dx = fmaf(v.x, w, dx);
            ssy = fmaf(v.y, v.y, ssy); dy = fmaf(v.y, w, dy);
            ssz = fmaf(v.z, v.z, ssz); dz = fmaf(v.z, w, dz);
            ssw = fmaf(v.w, v.w, ssw); dw = fmaf(v.w, w, dw);
        }
        float ex = pSx - __expf(sx  * dx * rsqrtf(fmaxf(ssx, 1e-24f)));
        float ey = pSy - __expf(sy  * dy * rsqrtf(fmaxf(ssy, 1e-24f)));
        float ez = pSz - __expf(sz  * dz * rsqrtf(fmaxf(ssz, 1e-24f)));
        float ew = pSw - __expf(sw4 * dw * rsqrtf(fmaxf(ssw, 1e-24f)));

        local = fmaf(ex, ex, local);
        local = fmaf(ey, ey, local);
        local = fmaf(ez, ez, local);
        local = fmaf(ew, ew, local);
    }

    local = warp_sum(local);
    if ((tid & 31) == 0) sred[tid >> 5] = local;
    __syncthreads();
    if (tid == 0) {
        float v = ((sred[0] + sred[1]) + (sred[2] + sred[3]))
                + ((sred[4] + sred[5]) + (sred[6] + sred[7]));
        g_p2[b][bx] = v;
        __threadfence();
        slast = (atomicAdd(&g_ctr, 1) == NB * 32 - 1) ? 1 : 0;
    }
    __syncthreads();

    // --- last block: deterministic fixed-structure final reduction ----------
    if (slast) {
        __threadfence();
        const float* p = (const float*)g_p2;
        float v = (p[tid] + p[tid + 256]) + (p[tid + 512] + p[tid + 768]);
        v = warp_sum(v);
        __syncthreads();                 // sred reuse
        if ((tid & 31) == 0) sred[tid >> 5] = v;
        __syncthreads();
        if (tid == 0) {
            float s = ((sred[0] + sred[1]) + (sred[2] + sred[3]))
                    + ((sred[4] + sred[5]) + (sred[6] + sred[7]));
            out[0] = s * (1.0f / (float)NPIX);
            atomicExch(&g_ctr, 0);       // reset for next graph replay
        }
    }
}

extern "C" void kernel_launch(void* const* d_in, const int* in_sizes, int n_in,
                              void* d_out, int out_size) {
    const float* S = (const float*)d_in[0];
    const float* T = (const float*)d_in[1];
    const int* tg = (const int*)d_in[2];
    float* out = (float*)d_out;

    dim3 g1(32, NB, 2);
    k_pass1<<<g1, 256>>>(S, T, tg);
    dim3 g2(32, NB);
    k_pass2<<<g2, 256>>>(S, T, tg, out);
}

// round 8
// speedup vs baseline: 1.1261x; 1.0184x over previous
#include <cuda_runtime.h>

#define NB   32
#define NCH  16
#define NP   65536              // 256*256 pixels per batch
#define NPIX (NB * NP)

// ---------------- scratch (device globals; no allocation allowed) ----------
// pass1 partials: [tensor][batch][block][ a0[16] | aAll[16] | cnt ]
__device__ float g_p1[2][NB][32][33];
__device__ float g_p2[NB][32];      // pass2 per-block MSE partials
__device__ int   g_ctr;             // last-block-done counter (self-resetting)

__device__ __forceinline__ float warp_sum(float v) {
#pragma unroll
    for (int off = 16; off; off >>= 1)
        v += __shfl_xor_sync(0xffffffffu, v, off);
    return v;
}

// ---------------- pass 1: class-conditional sums of normalized features ----
// grid (32, NB, 2), 256 threads. z selects tensor. float4 pixels, 2 iters.
__global__ __launch_bounds__(256, 2) void k_pass1(const float* __restrict__ S,
                                                  const float* __restrict__ T,
                                                  const int* __restrict__ tg) {
    const int bx  = blockIdx.x;
    const int b   = blockIdx.y;
    const int t   = blockIdx.z;
    const int tid = threadIdx.x;
    const float* X = t ? T : S;

    const float4* Xv = (const float4*)(X + (size_t)b * NCH * NP);
    const int4*   tv = (const int4*)(tg + (size_t)b * NP);

    float a0[NCH], aA[NCH];
#pragma unroll
    for (int c = 0; c < NCH; c++) { a0[c] = 0.f; aA[c] = 0.f; }
    float cnt = 0.f;

#pragma unroll 1
    for (int it = 0; it < 2; it++) {
        int p4 = (it * 32 + bx) * 256 + tid;       // float4 index in [0, NP/4)
        int4 tt = tv[p4];

        float4 v[NCH];
#pragma unroll
        for (int c = 0; c < NCH; c++) v[c] = Xv[c * (NP / 4) + p4];

        float mx = (tt.x == 0) ? 1.f : 0.f;
        float my = (tt.y == 0) ? 1.f : 0.f;
        float mz = (tt.z == 0) ? 1.f : 0.f;
        float mw = (tt.w == 0) ? 1.f : 0.f;
        cnt += (mx + my) + (mz + mw);

        float ssx = 0.f, ssy = 0.f, ssz = 0.f, ssw = 0.f;
#pragma unroll
        for (int c = 0; c < NCH; c++) {
            ssx = fmaf(v[c].x, v[c].x, ssx);
            ssy = fmaf(v[c].y, v[c].y, ssy);
            ssz = fmaf(v[c].z, v[c].z, ssz);
            ssw = fmaf(v[c].w, v[c].w, ssw);
        }
        // equals x / max(sqrt(ss), 1e-12) for representable inputs
        float ix = rsqrtf(fmaxf(ssx, 1e-24f));
        float iy = rsqrtf(fmaxf(ssy, 1e-24f));
        float iz = rsqrtf(fmaxf(ssz, 1e-24f));
        float iw = rsqrtf(fmaxf(ssw, 1e-24f));
        float wx = mx * ix, wy = my * iy, wz = mz * iz, ww = mw * iw;
#pragma unroll
        for (int c = 0; c < NCH; c++) {
            aA[c] = fmaf(v[c].w, iw, fmaf(v[c].z, iz, fmaf(v[c].y, iy, fmaf(v[c].x, ix, aA[c]))));
            a0[c] = fmaf(v[c].w, ww, fmaf(v[c].z, wz, fmaf(v[c].y, wy, fmaf(v[c].x, wx, a0[c]))));
        }
    }

    // block reduce 33 stats -> g_p1 (plain stores, no global atomics)
    __shared__ float sred[33];
    if (tid < 33) sred[tid] = 0.f;
    __syncthreads();
    bool lane0 = ((tid & 31) == 0);
#pragma unroll
    for (int c = 0; c < NCH; c++) {
        float r0 = warp_sum(a0[c]);
        float rA = warp_sum(aA[c]);
        if (lane0) { atomicAdd(&sred[c], r0); atomicAdd(&sred[16 + c], rA); }
    }
    float rc = warp_sum(cnt);
    if (lane0) atomicAdd(&sred[32], rc);
    __syncthreads();
    if (tid < 33) g_p1[t][b][bx][tid] = sred[tid];
}

// ---------------- pass 2: means prologue + pcsim + MSE + finalize ----------
// grid (32, NB), 256 threads, float4 pixels, 2 iters, staged wide loads
__global__ __launch_bounds__(256, 2) void k_pass2(const float* __restrict__ S,
                                                  const float* __restrict__ T,
                                                  const int* __restrict__ tg,
                                                  float* __restrict__ out) {
    __shared__ float ssum[66];
    __shared__ float sw[32];          // combined weight per [tensor][channel]
    __shared__ float sred[8];
    __shared__ int   slast;
    const int bx  = blockIdx.x;
    const int b   = blockIdx.y;
    const int tid = threadIdx.x;

    // --- prologue: reduce pass1 partials -> combined weights (redundant/block)
    if (tid < 66) {
        int t = tid / 33, s = tid - t * 33;
        float acc = 0.f;
#pragma unroll
        for (int k = 0; k < 32; k++) acc += g_p1[t][b][k][s];
        ssum[tid] = acc;
    }
    __syncthreads();
    if (tid < 64) {
        int t = tid >> 5, cls = (tid >> 4) & 1, c = tid & 15;
        float cnt0 = ssum[32];                     // count from tensor 0
        float s0 = ssum[t * 33 + c], sA = ssum[t * 33 + 16 + c];
        float m = (cls == 0) ? s0 / (cnt0 + 1e-6f)
                             : (sA - s0) / ((float)NP - cnt0 + 1e-6f);
        float n = m * m;                           // ||mean|| over 16 channels
#pragma unroll
        for (int off = 8; off; off >>= 1)
            n += __shfl_xor_sync(0xffffffffu, n, off);
        float rd = 1.0f / fmaxf(sqrtf(n), 1e-8f);
        float val = (cls == 0) ? m * rd : -(m * rd);
        float other = __shfl_xor_sync(0xffffffffu, val, 16);   // combine classes
        if (cls == 0) sw[t * 16 + c] = val + other;
    }
    __syncthreads();

    const float4* Sv = (const float4*)(S + (size_t)b * NCH * NP);
    const float4* Tv = (const float4*)(T + (size_t)b * NCH * NP);
    const int4*   tv = (const int4*)(tg + (size_t)b * NP);

    float local = 0.f;
#pragma unroll 1
    for (int it = 0; it < 2; it++) {
        int p4 = (it * 32 + bx) * 256 + tid;     // float4 index in [0, NP/4)
        int4 tt = tv[p4];
        float sx = (tt.x == 0) ? 1.f : -1.f;
        float sy = (tt.y == 0) ? 1.f : -1.f;
        float sz = (tt.z == 0) ? 1.f : -1.f;
        float sw4 = (tt.w == 0) ? 1.f : -1.f;

        // ---- S tensor: stage all 16 wide loads first (front-batched MLP) ----
        float4 v[NCH];
#pragma unroll
        for (int c = 0; c < NCH; c++) v[c] = Sv[c * (NP / 4) + p4];

        float ssx = 0.f, ssy = 0.f, ssz = 0.f, ssw = 0.f;
        float dx = 0.f, dy = 0.f, dz = 0.f, dw = 0.f;
#pragma unroll
        for (int c = 0; c < NCH; c++) {
            float w = sw[c];
            ssx = fmaf(v[c].x, v[c].x, ssx); dx = fmaf(v[c].x, w, dx);
            ssy = fmaf(v[c].y, v[c].y, ssy); dy = fmaf(v[c].y, w, dy);
            ssz = fmaf(v[c].z, v[c].z, ssz); dz = fmaf(v[c].z, w, dz);
            ssw = fmaf(v[c].w, v[c].w, ssw); dw = fmaf(v[c].w, w, dw);
        }
        float pSx = __expf(sx  * dx * rsqrtf(fmaxf(ssx, 1e-24f)));
        float pSy = __expf(sy  * dy * rsqrtf(fmaxf(ssy, 1e-24f)));
        float pSz = __expf(sz  * dz * rsqrtf(fmaxf(ssz, 1e-24f)));
        float pSw = __expf(sw4 * dw * rsqrtf(fmaxf(ssw, 1e-24f)));

        // ---- T tensor: same staging ----
#pragma unroll
        for (int c = 0; c < NCH; c++) v[c] = Tv[c * (NP / 4) + p4];

        ssx = ssy = ssz = ssw = 0.f;
        dx = dy = dz = dw = 0.f;
#pragma unroll
        for (int c = 0; c < NCH; c++) {
            float w = sw[16 + c];
            ssx = fmaf(v[c].x, v[c].x, ssx); dx = fmaf(v[c].x, w, dx);
            ssy = fmaf(v[c].y, v[c].y, ssy); dy = fmaf(v[c].y, w, dy);
            ssz = fmaf(v[c].z, v[c].z, ssz); dz = fmaf(v[c].z, w, dz);
            ssw = fmaf(v[c].w, v[c].w, ssw); dw = fmaf(v[c].w, w, dw);
        }
        float ex = pSx - __expf(sx  * dx * rsqrtf(fmaxf(ssx, 1e-24f)));
        float ey = pSy - __expf(sy  * dy * rsqrtf(fmaxf(ssy, 1e-24f)));
        float ez = pSz - __expf(sz  * dz * rsqrtf(fmaxf(ssz, 1e-24f)));
        float ew = pSw - __expf(sw4 * dw * rsqrtf(fmaxf(ssw, 1e-24f)));

        local = fmaf(ex, ex, local);
        local = fmaf(ey, ey, local);
        local = fmaf(ez, ez, local);
        local = fmaf(ew, ew, local);
    }

    local = warp_sum(local);
    if ((tid & 31) == 0) sred[tid >> 5] = local;
    __syncthreads();
    if (tid == 0) {
        float v = ((sred[0] + sred[1]) + (sred[2] + sred[3]))
                + ((sred[4] + sred[5]) + (sred[6] + sred[7]));
        g_p2[b][bx] = v;
        __threadfence();
        slast = (atomicAdd(&g_ctr, 1) == NB * 32 - 1) ? 1 : 0;
    }
    __syncthreads();

    // --- last block: deterministic fixed-structure final reduction ----------
    if (slast) {
        __threadfence();
        const float* p = (const float*)g_p2;
        float v = (p[tid] + p[tid + 256]) + (p[tid + 512] + p[tid + 768]);
        v = warp_sum(v);
        __syncthreads();                 // sred reuse
        if ((tid & 31) == 0) sred[tid >> 5] = v;
        __syncthreads();
        if (tid == 0) {
            float s = ((sred[0] + sred[1]) + (sred[2] + sred[3]))
                    + ((sred[4] + sred[5]) + (sred[6] + sred[7]));
            out[0] = s * (1.0f / (float)NPIX);
            atomicExch(&g_ctr, 0);       // reset for next graph replay
        }
    }
}

extern "C" void kernel_launch(void* const* d_in, const int* in_sizes, int n_in,
                              void* d_out, int out_size) {
    const float* S = (const float*)d_in[0];
    const float* T = (const float*)d_in[1];
    const int* tg = (const int*)d_in[2];
    float* out = (float*)d_out;

    dim3 g1(32, NB, 2);
    k_pass1<<<g1, 256>>>(S, T, tg);
    dim3 g2(32, NB);
    k_pass2<<<g2, 256>>>(S, T, tg, out);
}

// round 10
// speedup vs baseline: 1.4158x; 1.2572x over previous
#include <cuda_runtime.h>

#define NB   32
#define NCH  16
#define NP   65536              // 256*256 pixels per batch
#define NPIX (NB * NP)

// ---------------- scratch (device globals; no allocation allowed) ----------
// pass1 partials: [tensor][batch][block][ a0[16] | aAll[16] | cnt ]
__device__ float g_p1[2][NB][8][33];
__device__ float g_p2[NB][16];      // pass2 per-block MSE partials
__device__ int   g_ctr;             // last-block-done counter (self-resetting)

__device__ __forceinline__ float warp_sum(float v) {
#pragma unroll
    for (int off = 16; off; off >>= 1)
        v += __shfl_xor_sync(0xffffffffu, v, off);
    return v;
}

// ---------------- pass 1: class-conditional sums of normalized features ----
// grid (8, NB, 2), 256 threads. z selects tensor. float4 pixels, 8 iters.
__global__ __launch_bounds__(256, 2) void k_pass1(const float* __restrict__ S,
                                                  const float* __restrict__ T,
                                                  const int* __restrict__ tg) {
    const int bx  = blockIdx.x;
    const int b   = blockIdx.y;
    const int t   = blockIdx.z;
    const int tid = threadIdx.x;
    const float* X = t ? T : S;

    const float4* Xv = (const float4*)(X + (size_t)b * NCH * NP);
    const int4*   tv = (const int4*)(tg + (size_t)b * NP);

    float a0[NCH], aA[NCH];
#pragma unroll
    for (int c = 0; c < NCH; c++) { a0[c] = 0.f; aA[c] = 0.f; }
    float cnt = 0.f;

#pragma unroll 1
    for (int it = 0; it < 8; it++) {
        int p4 = (it * 8 + bx) * 256 + tid;        // float4 index in [0, NP/4)
        int4 tt = tv[p4];

        float4 v[NCH];
#pragma unroll
        for (int c = 0; c < NCH; c++) v[c] = Xv[c * (NP / 4) + p4];

        float mx = (tt.x == 0) ? 1.f : 0.f;
        float my = (tt.y == 0) ? 1.f : 0.f;
        float mz = (tt.z == 0) ? 1.f : 0.f;
        float mw = (tt.w == 0) ? 1.f : 0.f;
        cnt += (mx + my) + (mz + mw);

        float ssx = 0.f, ssy = 0.f, ssz = 0.f, ssw = 0.f;
#pragma unroll
        for (int c = 0; c < NCH; c++) {
            ssx = fmaf(v[c].x, v[c].x, ssx);
            ssy = fmaf(v[c].y, v[c].y, ssy);
            ssz = fmaf(v[c].z, v[c].z, ssz);
            ssw = fmaf(v[c].w, v[c].w, ssw);
        }
        // equals x / max(sqrt(ss), 1e-12) for representable inputs
        float ix = rsqrtf(fmaxf(ssx, 1e-24f));
        float iy = rsqrtf(fmaxf(ssy, 1e-24f));
        float iz = rsqrtf(fmaxf(ssz, 1e-24f));
        float iw = rsqrtf(fmaxf(ssw, 1e-24f));
        float wx = mx * ix, wy = my * iy, wz = mz * iz, ww = mw * iw;
#pragma unroll
        for (int c = 0; c < NCH; c++) {
            aA[c] = fmaf(v[c].w, iw, fmaf(v[c].z, iz, fmaf(v[c].y, iy, fmaf(v[c].x, ix, aA[c]))));
            a0[c] = fmaf(v[c].w, ww, fmaf(v[c].z, wz, fmaf(v[c].y, wy, fmaf(v[c].x, wx, a0[c]))));
        }
    }

    // block reduce 33 stats: per-warp rows (no atomics), then 33-thread sum
    __shared__ float sredw[8][33];
    const int wid = tid >> 5;
    bool lane0 = ((tid & 31) == 0);
#pragma unroll
    for (int c = 0; c < NCH; c++) {
        float r0 = warp_sum(a0[c]);
        float rA = warp_sum(aA[c]);
        if (lane0) { sredw[wid][c] = r0; sredw[wid][16 + c] = rA; }
    }
    float rc = warp_sum(cnt);
    if (lane0) sredw[wid][32] = rc;
    __syncthreads();
    if (tid < 33) {
        float acc = 0.f;
#pragma unroll
        for (int w = 0; w < 8; w++) acc += sredw[w][tid];
        g_p1[t][b][bx][tid] = acc;
    }
}

// ---------------- pass 2: means prologue + pcsim + MSE + finalize ----------
// grid (16, NB), 256 threads, float4 pixels, 4 iters, staged wide loads
__global__ __launch_bounds__(256, 2) void k_pass2(const float* __restrict__ S,
                                                  const float* __restrict__ T,
                                                  const int* __restrict__ tg,
                                                  float* __restrict__ out) {
    __shared__ float ssum[66];
    __shared__ float sw[32];          // combined weight per [tensor][channel]
    __shared__ float sred[8];
    __shared__ int   slast;
    const int bx  = blockIdx.x;
    const int b   = blockIdx.y;
    const int tid = threadIdx.x;

    // --- prologue: reduce pass1 partials -> combined weights (redundant/block)
    if (tid < 66) {
        int t = tid / 33, s = tid - t * 33;
        float acc = 0.f;
#pragma unroll
        for (int k = 0; k < 8; k++) acc += g_p1[t][b][k][s];
        ssum[tid] = acc;
    }
    __syncthreads();
    if (tid < 64) {
        int t = tid >> 5, cls = (tid >> 4) & 1, c = tid & 15;
        float cnt0 = ssum[32];                     // count from tensor 0
        float s0 = ssum[t * 33 + c], sA = ssum[t * 33 + 16 + c];
        float m = (cls == 0) ? s0 / (cnt0 + 1e-6f)
                             : (sA - s0) / ((float)NP - cnt0 + 1e-6f);
        float n = m * m;                           // ||mean|| over 16 channels
#pragma unroll
        for (int off = 8; off; off >>= 1)
            n += __shfl_xor_sync(0xffffffffu, n, off);
        float rd = 1.0f / fmaxf(sqrtf(n), 1e-8f);
        float val = (cls == 0) ? m * rd : -(m * rd);
        float other = __shfl_xor_sync(0xffffffffu, val, 16);   // combine classes
        if (cls == 0) sw[t * 16 + c] = val + other;
    }
    __syncthreads();

    const float4* Sv = (const float4*)(S + (size_t)b * NCH * NP);
    const float4* Tv = (const float4*)(T + (size_t)b * NCH * NP);
    const int4*   tv = (const int4*)(tg + (size_t)b * NP);

    float local = 0.f;
#pragma unroll 1
    for (int it = 0; it < 4; it++) {
        int p4 = (it * 16 + bx) * 256 + tid;     // float4 index in [0, NP/4)
        int4 tt = tv[p4];
        float sx = (tt.x == 0) ? 1.f : -1.f;
        float sy = (tt.y == 0) ? 1.f : -1.f;
        float sz = (tt.z == 0) ? 1.f : -1.f;
        float sw4 = (tt.w == 0) ? 1.f : -1.f;

        // ---- S tensor: stage all 16 wide loads first (front-batched MLP) ----
        float4 v[NCH];
#pragma unroll
        for (int c = 0; c < NCH; c++) v[c] = Sv[c * (NP / 4) + p4];

        float ssx = 0.f, ssy = 0.f, ssz = 0.f, ssw = 0.f;
        float dx = 0.f, dy = 0.f, dz = 0.f, dw = 0.f;
#pragma unroll
        for (int c = 0; c < NCH; c++) {
            float w = sw[c];
            ssx = fmaf(v[c].x, v[c].x, ssx); dx = fmaf(v[c].x, w, dx);
            ssy = fmaf(v[c].y, v[c].y, ssy); dy = fmaf(v[c].y, w, dy);
            ssz = fmaf(v[c].z, v[c].z, ssz); dz = fmaf(v[c].z, w, dz);
            ssw = fmaf(v[c].w, v[c].w, ssw); dw = fmaf(v[c].w, w, dw);
        }
        float pSx = __expf(sx  * dx * rsqrtf(fmaxf(ssx, 1e-24f)));
        float pSy = __expf(sy  * dy * rsqrtf(fmaxf(ssy, 1e-24f)));
        float pSz = __expf(sz  * dz * rsqrtf(fmaxf(ssz, 1e-24f)));
        float pSw = __expf(sw4 * dw * rsqrtf(fmaxf(ssw, 1e-24f)));

        // ---- T tensor: same staging ----
#pragma unroll
        for (int c = 0; c < NCH; c++) v[c] = Tv[c * (NP / 4) + p4];

        ssx = ssy = ssz = ssw = 0.f;
        dx = dy = dz = dw = 0.f;
#pragma unroll
        for (int c = 0; c < NCH; c++) {
            float w = sw[16 + c];
            ssx = fmaf(v[c].x, v[c].x, ssx); dx = fmaf(v[c].x, w, dx);
            ssy = fmaf(v[c].y, v[c].y, ssy); dy = fmaf(v[c].y, w, dy);
            ssz = fmaf(v[c].z, v[c].z, ssz); dz = fmaf(v[c].z, w, dz);
            ssw = fmaf(v[c].w, v[c].w, ssw); dw = fmaf(v[c].w, w, dw);
        }
        float ex = pSx - __expf(sx  * dx * rsqrtf(fmaxf(ssx, 1e-24f)));
        float ey = pSy - __expf(sy  * dy * rsqrtf(fmaxf(ssy, 1e-24f)));
        float ez = pSz - __expf(sz  * dz * rsqrtf(fmaxf(ssz, 1e-24f)));
        float ew = pSw - __expf(sw4 * dw * rsqrtf(fmaxf(ssw, 1e-24f)));

        local = fmaf(ex, ex, local);
        local = fmaf(ey, ey, local);
        local = fmaf(ez, ez, local);
        local = fmaf(ew, ew, local);
    }

    local = warp_sum(local);
    if ((tid & 31) == 0) sred[tid >> 5] = local;
    __syncthreads();
    if (tid == 0) {
        float v = ((sred[0] + sred[1]) + (sred[2] + sred[3]))
                + ((sred[4] + sred[5]) + (sred[6] + sred[7]));
        g_p2[b][bx] = v;
        __threadfence();
        slast = (atomicAdd(&g_ctr, 1) == NB * 16 - 1) ? 1 : 0;
    }
    __syncthreads();

    // --- last block: deterministic fixed-structure final reduction ----------
    if (slast) {
        __threadfence();
        const float* p = (const float*)g_p2;
        float v = p[tid] + p[tid + 256];          // 512 partials
        v = warp_sum(v);
        __syncthreads();                 // sred reuse
        if ((tid & 31) == 0) sred[tid >> 5] = v;
        __syncthreads();
        if (tid == 0) {
            float s = ((sred[0] + sred[1]) + (sred[2] + sred[3]))
                    + ((sred[4] + sred[5]) + (sred[6] + sred[7]));
            out[0] = s * (1.0f / (float)NPIX);
            atomicExch(&g_ctr, 0);       // reset for next graph replay
        }
    }
}

extern "C" void kernel_launch(void* const* d_in, const int* in_sizes, int n_in,
                              void* d_out, int out_size) {
    const float* S = (const float*)d_in[0];
    const float* T = (const float*)d_in[1];
    const int* tg = (const int*)d_in[2];
    float* out = (float*)d_out;

    dim3 g1(8, NB, 2);
    k_pass1<<<g1, 256>>>(S, T, tg);
    dim3 g2(16, NB);
    k_pass2<<<g2, 256>>>(S, T, tg, out);
}